// round 9
// baseline (speedup 1.0000x reference)
#include <cuda_runtime.h>
#include <cuda_bf16.h>
#include <math.h>

#define BB 16
#define HH 480
#define WW 640
#define HW (HH*WW)
#define CC 256
#define HCC 60
#define WCC 80
#define KK 400
#define CAND_CAP 24576

#define CH 10               // output rows per block (best measured config)
#define NBY (HH / CH)       // 48
#define NT 160              // threads per block = 640/4 columns
#define SBUF 1024           // per-block candidate staging capacity

// output layout: kpts (16,400,2) | scores (16,400) | sampled (16,256,400) | heatmap (16,1,480,640)
#define OFF_KPTS 0
#define OFF_SCORES (BB*KK*2)
#define OFF_SAMPLED (OFF_SCORES + BB*KK)
#define OFF_HEAT (OFF_SAMPLED + BB*CC*KK)

__device__ unsigned int g_cval[BB*CAND_CAP];
__device__ unsigned int g_cidx[BB*CAND_CAP];
__device__ int g_count[BB];      // zero at load; re-zeroed by k_select tail each replay
__device__ int g_topidx[BB*KK];

// Fused NMS: heatmap copy + separable 7x7 max + compaction.
// grid (NBY, BB), block 160. Thread = 4 consecutive columns (one float4).
__global__ __launch_bounds__(NT) void k_nms(const float* __restrict__ h,
                                            float* __restrict__ out) {
    __shared__ unsigned int s_val[SBUF];
    __shared__ unsigned int s_idx[SBUF];
    __shared__ int s_cnt;
    __shared__ int s_base;

    int b   = blockIdx.y;
    int ty0 = blockIdx.x * CH;
    int tid = threadIdx.x;
    if (tid == 0) s_cnt = 0;
    __syncthreads();

    const float4* hb4 = reinterpret_cast<const float4*>(h + (size_t)b*HW);
    float4*       ob4 = reinterpret_cast<float4*>(out + OFF_HEAT + (size_t)b*HW);
    int xb = tid * 4;

    float4 zero4 = make_float4(0.f, 0.f, 0.f, 0.f);
    float4 w0=zero4,w1=zero4,w2=zero4,w3=zero4,w4=zero4,w5=zero4,w6=zero4;
    float4 d0=zero4,d1=zero4,d2=zero4;

    #pragma unroll
    for (int t = 0; t < CH + 6; ++t) {
        int yy = ty0 - 3 + t;
        float4 qm = zero4, qc = zero4, qp = zero4;
        if (yy >= 0 && yy < HH) {
            int rb = yy * (WW/4);
            qc = __ldg(hb4 + rb + tid);
            if (tid > 0)      qm = __ldg(hb4 + rb + tid - 1);
            if (tid < NT - 1) qp = __ldg(hb4 + rb + tid + 1);
            if (t >= 3 && t < CH + 3) ob4[rb + tid] = qc;
        }
        float p1 = fmaxf(qm.y, qm.z);
        float p2 = fmaxf(qm.z, qm.w);
        float p3 = fmaxf(qm.w, qc.x);
        float p4 = fmaxf(qc.x, qc.y);
        float p5 = fmaxf(qc.y, qc.z);
        float p6 = fmaxf(qc.z, qc.w);
        float p7 = fmaxf(qc.w, qp.x);
        float p8 = fmaxf(qp.x, qp.y);
        float4 rm;
        rm.x = fmaxf(fmaxf(p1, p3), fmaxf(p5, qc.w));
        rm.y = fmaxf(fmaxf(p2, p4), fmaxf(p6, qp.x));
        rm.z = fmaxf(fmaxf(p3, p5), fmaxf(p7, qp.y));
        rm.w = fmaxf(fmaxf(p4, p6), fmaxf(p8, qp.z));

        float4 vcand = d0;
        d0 = d1; d1 = d2; d2 = qc;
        w0 = w1; w1 = w2; w2 = w3; w3 = w4; w4 = w5; w5 = w6; w6 = rm;

        if (t >= 6) {
            int yc = yy - 3;
            if (yc >= 4 && yc < HH - 4) {
                float4 m;
                m.x = fmaxf(fmaxf(fmaxf(w0.x,w1.x),fmaxf(w2.x,w3.x)),
                            fmaxf(fmaxf(w4.x,w5.x),w6.x));
                m.y = fmaxf(fmaxf(fmaxf(w0.y,w1.y),fmaxf(w2.y,w3.y)),
                            fmaxf(fmaxf(w4.y,w5.y),w6.y));
                m.z = fmaxf(fmaxf(fmaxf(w0.z,w1.z),fmaxf(w2.z,w3.z)),
                            fmaxf(fmaxf(w4.z,w5.z),w6.z));
                m.w = fmaxf(fmaxf(fmaxf(w0.w,w1.w),fmaxf(w2.w,w3.w)),
                            fmaxf(fmaxf(w4.w,w5.w),w6.w));
                float vj[4] = {vcand.x, vcand.y, vcand.z, vcand.w};
                float mj[4] = {m.x, m.y, m.z, m.w};
                #pragma unroll
                for (int j = 0; j < 4; ++j) {
                    int x = xb + j;
                    if (x >= 4 && x < WW-4 && vj[j] > 0.f && vj[j] >= mj[j]) {
                        int p = atomicAdd(&s_cnt, 1);
                        if (p < SBUF) {
                            s_val[p] = 0xFFFFFFFFu - __float_as_uint(vj[j]);
                            s_idx[p] = (unsigned)(yc*WW + x);
                        }
                    }
                }
            }
        }
    }

    __syncthreads();
    int cnt = s_cnt; if (cnt > SBUF) cnt = SBUF;
    if (tid == 0) s_base = atomicAdd(&g_count[b], cnt);
    __syncthreads();
    int base = s_base;
    for (int i = tid; i < cnt; i += NT) {
        int slot = base + i;
        if (slot < CAND_CAP) {
            g_cval[b*CAND_CAP + slot] = s_val[i];
            g_cidx[b*CAND_CAP + slot] = s_idx[i];
        }
    }
}

// exact per-batch top-K: 3-pass wide radix-select + gather + rank-by-count.
__global__ __launch_bounds__(1024) void k_select(float* __restrict__ out) {
    __shared__ unsigned int bins[2048];
    __shared__ int s_warp[32];
    __shared__ unsigned int s_bin;
    __shared__ int s_newrank;
    __shared__ unsigned long long s_keys[512];
    __shared__ int s_cnt;

    int b = blockIdx.x;
    int tid = threadIdx.x;
    int lane = tid & 31, wid = tid >> 5;
    int n = g_count[b]; if (n > CAND_CAP) n = CAND_CAP;
    const unsigned int* vals = g_cval + (size_t)b*CAND_CAP;
    const unsigned int* idxs = g_cidx + (size_t)b*CAND_CAP;

    int nIter = (n + 1023) >> 10;
    unsigned int pivot = 0xFFFFFFFFu;
    int rank = KK;

    if (n >= KK) {
        unsigned int prefix = 0;
        #pragma unroll
        for (int p = 0; p < 3; ++p) {
            int shift    = (p == 0) ? 21 : (p == 1) ? 10 : 0;
            int nbins    = (p == 2) ? 1024 : 2048;
            int topshift = shift + ((p == 2) ? 10 : 11);

            for (int i = tid; i < nbins; i += 1024) bins[i] = 0;
            __syncthreads();

            for (int it = 0; it < nIter; ++it) {
                int i = (it << 10) + tid;
                bool active = (i < n);
                unsigned int vk = active ? vals[i] : 0u;
                bool ok = active && ((p == 0) || ((vk >> topshift) == prefix));
                unsigned int bin = (vk >> shift) & (unsigned)(nbins - 1);
                unsigned int m = __ballot_sync(0xFFFFFFFFu, ok);
                if (ok) {
                    unsigned int peers = __match_any_sync(m, bin);
                    int ldr = __ffs(peers) - 1;
                    if (lane == ldr) atomicAdd(&bins[bin], (unsigned)__popc(peers));
                }
            }
            __syncthreads();

            int c0 = 0, c1 = 0;
            if (2*tid < nbins) { c0 = (int)bins[2*tid]; c1 = (int)bins[2*tid + 1]; }
            int s = c0 + c1;
            int v2 = s;
            #pragma unroll
            for (int o = 1; o < 32; o <<= 1) {
                int t = __shfl_up_sync(0xFFFFFFFFu, v2, o);
                if (lane >= o) v2 += t;
            }
            if (lane == 31) s_warp[wid] = v2;
            __syncthreads();
            if (wid == 0) {
                int ws = s_warp[lane];
                #pragma unroll
                for (int o = 1; o < 32; o <<= 1) {
                    int t = __shfl_up_sync(0xFFFFFFFFu, ws, o);
                    if (lane >= o) ws += t;
                }
                s_warp[lane] = ws;
            }
            __syncthreads();
            int incl = v2 + (wid > 0 ? s_warp[wid - 1] : 0);
            int excl = incl - s;
            if (rank > excl && rank <= excl + c0) {
                s_bin = (unsigned)(2*tid); s_newrank = rank - excl;
            } else if (rank > excl + c0 && rank <= incl) {
                s_bin = (unsigned)(2*tid + 1); s_newrank = rank - excl - c0;
            }
            __syncthreads();
            prefix = (p == 0) ? s_bin : ((prefix << ((p == 2) ? 10 : 11)) | s_bin);
            rank = s_newrank;
            __syncthreads();
        }
        pivot = prefix;
    }

    if (tid == 0) s_cnt = 0;
    __syncthreads();
    #pragma unroll
    for (int phase = 0; phase < 2; ++phase) {
        for (int it = 0; it < nIter; ++it) {
            int i = (it << 10) + tid;
            bool active = (i < n);
            unsigned int vk = active ? vals[i] : 0u;
            bool take = active && ((phase == 0) ? (vk < pivot) : (vk == pivot));
            unsigned int m = __ballot_sync(0xFFFFFFFFu, take);
            if (take) {
                int ldr = __ffs(m) - 1;
                int base;
                if (lane == ldr) base = atomicAdd(&s_cnt, __popc(m));
                base = __shfl_sync(m, base, ldr);
                int slot = base + __popc(m & ((1u << lane) - 1u));
                if (slot < 512)
                    s_keys[slot] = ((unsigned long long)vk << 32) | idxs[i];
            }
        }
        __syncthreads();
    }
    int cnt = s_cnt; if (cnt > 512) cnt = 512;
    for (int i = tid; i < 512; i += 1024)
        if (i >= cnt) s_keys[i] = ~0ULL;
    __syncthreads();

    // rank-by-count (barrier-free, LDS broadcast); keys unique -> permutation.
    if (tid < cnt) {
        unsigned long long key = s_keys[tid];
        int r = 0;
        #pragma unroll 8
        for (int j = 0; j < 512; ++j)
            r += (s_keys[j] < key) ? 1 : 0;
        if (r < KK) {
            unsigned int vb = 0xFFFFFFFFu - (unsigned int)(key >> 32);
            int idx = (int)(unsigned int)(key & 0xFFFFFFFFu);
            int y = idx / WW;
            int x = idx - y*WW;
            out[OFF_KPTS + ((size_t)b*KK + r)*2 + 0] = (float)x + 0.5f;
            out[OFF_KPTS + ((size_t)b*KK + r)*2 + 1] = (float)y + 0.5f;
            out[OFF_SCORES + (size_t)b*KK + r] = __uint_as_float(vb);
            g_topidx[b*KK + r] = idx;
        }
    }

    if (tid == 0) g_count[b] = 0;
}

// bilinear descriptor sample + L2 norm. grid (KK/8, BB), block 256 (thread = channel).
// ALL corner loads issued up-front (MLP ~16-20) before any compute; per-warp
// partial norms staged in smem (no smem atomics); contiguous float4 writes.
__global__ __launch_bounds__(256, 3) void k_sample(const float* __restrict__ desc,
                                                   float* __restrict__ out) {
    __shared__ int   s_a0[8];
    __shared__ int   s_a1[8];
    __shared__ int   s_sh[8];
    __shared__ float s_wq[8][4];
    __shared__ float s_wsum[8][8];   // [warp][kpt]
    __shared__ float s_inv[8];

    int b  = blockIdx.y;
    int k0 = blockIdx.x * 8;
    int c  = threadIdx.x;
    int lane = c & 31;
    int wrp  = c >> 5;

    if (c < 8) {
        int idx = g_topidx[b*KK + k0 + c];
        int iy = idx / WW;
        int ix = idx - iy*WW;
        float kx = (float)ix + 0.5f;
        float ky = (float)iy + 0.5f;
        float ux = (kx - 3.5f) / 635.5f;
        float uy = (ky - 3.5f) / 475.5f;
        float gx = ((ux * 2.f - 1.f) + 1.f) * 0.5f * (float)(WCC - 1);
        float gy = ((uy * 2.f - 1.f) + 1.f) * 0.5f * (float)(HCC - 1);
        float x0f = floorf(gx), y0f = floorf(gy);
        float wx = gx - x0f, wy = gy - y0f;
        int x0 = (int)x0f;
        int y0 = (int)y0f;
        int off0 = y0*WCC + x0;
        int off1 = (y0+1)*WCC + x0;
        s_sh[c] = x0 & 3;
        s_a0[c] = off0 >> 2;
        s_a1[c] = off1 >> 2;
        s_wq[c][0] = (1.f - wx) * (1.f - wy);
        s_wq[c][1] = wx * (1.f - wy);
        s_wq[c][2] = (1.f - wx) * wy;
        s_wq[c][3] = wx * wy;
    }
    __syncthreads();

    const float*  dp = desc + ((size_t)b*CC + c) * (HCC*WCC);
    const float4* d4 = reinterpret_cast<const float4*>(dp);

    // ---- load phase: all gathers in flight before any use ----
    float4 q0[8], q1[8];
    float  x0e[8], x1e[8];
    #pragma unroll
    for (int kk = 0; kk < 8; ++kk) {
        q0[kk] = __ldg(d4 + s_a0[kk]);
        q1[kk] = __ldg(d4 + s_a1[kk]);
    }
    #pragma unroll
    for (int kk = 0; kk < 8; ++kk) {
        if (s_sh[kk] == 3) {                 // uniform per kk across the block
            x0e[kk] = __ldg(dp + s_a0[kk]*4 + 4);
            x1e[kk] = __ldg(dp + s_a1[kk]*4 + 4);
        } else { x0e[kk] = 0.f; x1e[kk] = 0.f; }
    }

    // ---- compute phase ----
    float vv[8];
    float partial[8];
    #pragma unroll
    for (int kk = 0; kk < 8; ++kk) {
        int sh = s_sh[kk];
        float e00, e01, e10, e11;
        if (sh == 0)      { e00 = q0[kk].x; e01 = q0[kk].y; e10 = q1[kk].x; e11 = q1[kk].y; }
        else if (sh == 1) { e00 = q0[kk].y; e01 = q0[kk].z; e10 = q1[kk].y; e11 = q1[kk].z; }
        else if (sh == 2) { e00 = q0[kk].z; e01 = q0[kk].w; e10 = q1[kk].z; e11 = q1[kk].w; }
        else              { e00 = q0[kk].w; e01 = x0e[kk];  e10 = q1[kk].w; e11 = x1e[kk]; }
        float v = e00*s_wq[kk][0] + e01*s_wq[kk][1]
                + e10*s_wq[kk][2] + e11*s_wq[kk][3];
        vv[kk] = v;
        partial[kk] = v * v;
    }
    // warp reduce each kpt's partial, stage per-warp sums
    #pragma unroll
    for (int kk = 0; kk < 8; ++kk) {
        float s = partial[kk];
        #pragma unroll
        for (int o = 16; o > 0; o >>= 1) s += __shfl_xor_sync(0xFFFFFFFFu, s, o);
        if (lane == 0) s_wsum[wrp][kk] = s;
    }
    __syncthreads();
    if (c < 8) {
        float t = 0.f;
        #pragma unroll
        for (int w = 0; w < 8; ++w) t += s_wsum[w][c];
        s_inv[c] = 1.0f / sqrtf(t + 1e-12f);
    }
    __syncthreads();

    float4 o0, o1;
    o0.x = vv[0]*s_inv[0]; o0.y = vv[1]*s_inv[1];
    o0.z = vv[2]*s_inv[2]; o0.w = vv[3]*s_inv[3];
    o1.x = vv[4]*s_inv[4]; o1.y = vv[5]*s_inv[5];
    o1.z = vv[6]*s_inv[6]; o1.w = vv[7]*s_inv[7];
    float4* op = reinterpret_cast<float4*>(out + OFF_SAMPLED + ((size_t)b*CC + c)*KK + k0);
    op[0] = o0;
    op[1] = o1;
}

extern "C" void kernel_launch(void* const* d_in, const int* in_sizes, int n_in,
                              void* d_out, int out_size) {
    const float* heat = (const float*)d_in[0];
    const float* desc = (const float*)d_in[1];
    float* out = (float*)d_out;

    dim3 ngrid(NBY, BB);
    k_nms<<<ngrid, NT>>>(heat, out);

    k_select<<<BB, 1024>>>(out);

    dim3 sgrid(KK / 8, BB);
    k_sample<<<sgrid, 256>>>(desc, out);
}

// round 10
// speedup vs baseline: 1.1194x; 1.1194x over previous
#include <cuda_runtime.h>
#include <cuda_bf16.h>
#include <math.h>

#define BB 16
#define HH 480
#define WW 640
#define HW (HH*WW)
#define CC 256
#define HCC 60
#define WCC 80
#define KK 400
#define CAND_CAP 24576

#define CH 10               // output rows per block (best measured config)
#define NBY (HH / CH)       // 48
#define NT 160              // threads per block = 640/4 columns
#define SBUF 1024           // per-block candidate staging capacity

// output layout: kpts (16,400,2) | scores (16,400) | sampled (16,256,400) | heatmap (16,1,480,640)
#define OFF_KPTS 0
#define OFF_SCORES (BB*KK*2)
#define OFF_SAMPLED (OFF_SCORES + BB*KK)
#define OFF_HEAT (OFF_SAMPLED + BB*CC*KK)

__device__ unsigned int g_cval[BB*CAND_CAP];
__device__ unsigned int g_cidx[BB*CAND_CAP];
__device__ int g_count[BB];      // zero at load; re-zeroed by k_select tail each replay
__device__ int g_topidx[BB*KK];

// Fused NMS: heatmap copy + separable 7x7 max + compaction.
// grid (NBY, BB), block 160. Thread = 4 consecutive columns (one float4).
__global__ __launch_bounds__(NT) void k_nms(const float* __restrict__ h,
                                            float* __restrict__ out) {
    __shared__ unsigned int s_val[SBUF];
    __shared__ unsigned int s_idx[SBUF];
    __shared__ int s_cnt;
    __shared__ int s_base;

    int b   = blockIdx.y;
    int ty0 = blockIdx.x * CH;
    int tid = threadIdx.x;
    if (tid == 0) s_cnt = 0;
    __syncthreads();

    const float4* hb4 = reinterpret_cast<const float4*>(h + (size_t)b*HW);
    float4*       ob4 = reinterpret_cast<float4*>(out + OFF_HEAT + (size_t)b*HW);
    int xb = tid * 4;

    float4 zero4 = make_float4(0.f, 0.f, 0.f, 0.f);
    float4 w0=zero4,w1=zero4,w2=zero4,w3=zero4,w4=zero4,w5=zero4,w6=zero4;
    float4 d0=zero4,d1=zero4,d2=zero4;

    #pragma unroll
    for (int t = 0; t < CH + 6; ++t) {
        int yy = ty0 - 3 + t;
        float4 qm = zero4, qc = zero4, qp = zero4;
        if (yy >= 0 && yy < HH) {
            int rb = yy * (WW/4);
            qc = __ldg(hb4 + rb + tid);
            if (tid > 0)      qm = __ldg(hb4 + rb + tid - 1);
            if (tid < NT - 1) qp = __ldg(hb4 + rb + tid + 1);
            if (t >= 3 && t < CH + 3) ob4[rb + tid] = qc;
        }
        float p1 = fmaxf(qm.y, qm.z);
        float p2 = fmaxf(qm.z, qm.w);
        float p3 = fmaxf(qm.w, qc.x);
        float p4 = fmaxf(qc.x, qc.y);
        float p5 = fmaxf(qc.y, qc.z);
        float p6 = fmaxf(qc.z, qc.w);
        float p7 = fmaxf(qc.w, qp.x);
        float p8 = fmaxf(qp.x, qp.y);
        float4 rm;
        rm.x = fmaxf(fmaxf(p1, p3), fmaxf(p5, qc.w));
        rm.y = fmaxf(fmaxf(p2, p4), fmaxf(p6, qp.x));
        rm.z = fmaxf(fmaxf(p3, p5), fmaxf(p7, qp.y));
        rm.w = fmaxf(fmaxf(p4, p6), fmaxf(p8, qp.z));

        float4 vcand = d0;
        d0 = d1; d1 = d2; d2 = qc;
        w0 = w1; w1 = w2; w2 = w3; w3 = w4; w4 = w5; w5 = w6; w6 = rm;

        if (t >= 6) {
            int yc = yy - 3;
            if (yc >= 4 && yc < HH - 4) {
                float4 m;
                m.x = fmaxf(fmaxf(fmaxf(w0.x,w1.x),fmaxf(w2.x,w3.x)),
                            fmaxf(fmaxf(w4.x,w5.x),w6.x));
                m.y = fmaxf(fmaxf(fmaxf(w0.y,w1.y),fmaxf(w2.y,w3.y)),
                            fmaxf(fmaxf(w4.y,w5.y),w6.y));
                m.z = fmaxf(fmaxf(fmaxf(w0.z,w1.z),fmaxf(w2.z,w3.z)),
                            fmaxf(fmaxf(w4.z,w5.z),w6.z));
                m.w = fmaxf(fmaxf(fmaxf(w0.w,w1.w),fmaxf(w2.w,w3.w)),
                            fmaxf(fmaxf(w4.w,w5.w),w6.w));
                float vj[4] = {vcand.x, vcand.y, vcand.z, vcand.w};
                float mj[4] = {m.x, m.y, m.z, m.w};
                #pragma unroll
                for (int j = 0; j < 4; ++j) {
                    int x = xb + j;
                    if (x >= 4 && x < WW-4 && vj[j] > 0.f && vj[j] >= mj[j]) {
                        int p = atomicAdd(&s_cnt, 1);
                        if (p < SBUF) {
                            s_val[p] = 0xFFFFFFFFu - __float_as_uint(vj[j]);
                            s_idx[p] = (unsigned)(yc*WW + x);
                        }
                    }
                }
            }
        }
    }

    __syncthreads();
    int cnt = s_cnt; if (cnt > SBUF) cnt = SBUF;
    if (tid == 0) s_base = atomicAdd(&g_count[b], cnt);
    __syncthreads();
    int base = s_base;
    for (int i = tid; i < cnt; i += NT) {
        int slot = base + i;
        if (slot < CAND_CAP) {
            g_cval[b*CAND_CAP + slot] = s_val[i];
            g_cidx[b*CAND_CAP + slot] = s_idx[i];
        }
    }
}

// exact per-batch top-K: 3-pass wide radix-select on 32-bit complemented value,
// then gather <=512 survivors and bitonic sort by (value,idx). One block/batch.
__global__ __launch_bounds__(1024) void k_select(float* __restrict__ out) {
    __shared__ unsigned int bins[2048];
    __shared__ int s_warp[32];
    __shared__ unsigned int s_bin;
    __shared__ int s_newrank;
    __shared__ unsigned long long s_keys[512];
    __shared__ int s_cnt;

    int b = blockIdx.x;
    int tid = threadIdx.x;
    int lane = tid & 31, wid = tid >> 5;
    int n = g_count[b]; if (n > CAND_CAP) n = CAND_CAP;
    const unsigned int* vals = g_cval + (size_t)b*CAND_CAP;
    const unsigned int* idxs = g_cidx + (size_t)b*CAND_CAP;

    int nIter = (n + 1023) >> 10;
    unsigned int pivot = 0xFFFFFFFFu;
    int rank = KK;

    if (n >= KK) {
        unsigned int prefix = 0;
        #pragma unroll
        for (int p = 0; p < 3; ++p) {
            int shift    = (p == 0) ? 21 : (p == 1) ? 10 : 0;
            int nbins    = (p == 2) ? 1024 : 2048;
            int topshift = shift + ((p == 2) ? 10 : 11);

            for (int i = tid; i < nbins; i += 1024) bins[i] = 0;
            __syncthreads();

            for (int it = 0; it < nIter; ++it) {      // uniform trip count
                int i = (it << 10) + tid;
                bool active = (i < n);
                unsigned int vk = active ? vals[i] : 0u;
                bool ok = active && ((p == 0) || ((vk >> topshift) == prefix));
                unsigned int bin = (vk >> shift) & (unsigned)(nbins - 1);
                unsigned int m = __ballot_sync(0xFFFFFFFFu, ok);
                if (ok) {
                    unsigned int peers = __match_any_sync(m, bin);
                    int ldr = __ffs(peers) - 1;
                    if (lane == ldr) atomicAdd(&bins[bin], (unsigned)__popc(peers));
                }
            }
            __syncthreads();

            int c0 = 0, c1 = 0;
            if (2*tid < nbins) { c0 = (int)bins[2*tid]; c1 = (int)bins[2*tid + 1]; }
            int s = c0 + c1;
            int v2 = s;
            #pragma unroll
            for (int o = 1; o < 32; o <<= 1) {
                int t = __shfl_up_sync(0xFFFFFFFFu, v2, o);
                if (lane >= o) v2 += t;
            }
            if (lane == 31) s_warp[wid] = v2;
            __syncthreads();
            if (wid == 0) {
                int ws = s_warp[lane];
                #pragma unroll
                for (int o = 1; o < 32; o <<= 1) {
                    int t = __shfl_up_sync(0xFFFFFFFFu, ws, o);
                    if (lane >= o) ws += t;
                }
                s_warp[lane] = ws;
            }
            __syncthreads();
            int incl = v2 + (wid > 0 ? s_warp[wid - 1] : 0);
            int excl = incl - s;
            if (rank > excl && rank <= excl + c0) {
                s_bin = (unsigned)(2*tid); s_newrank = rank - excl;
            } else if (rank > excl + c0 && rank <= incl) {
                s_bin = (unsigned)(2*tid + 1); s_newrank = rank - excl - c0;
            }
            __syncthreads();
            prefix = (p == 0) ? s_bin : ((prefix << ((p == 2) ? 10 : 11)) | s_bin);
            rank = s_newrank;
            __syncthreads();
        }
        pivot = prefix;
    }

    // gather: strictly-less first (count < KK guaranteed), then equals
    if (tid == 0) s_cnt = 0;
    __syncthreads();
    #pragma unroll
    for (int phase = 0; phase < 2; ++phase) {
        for (int it = 0; it < nIter; ++it) {
            int i = (it << 10) + tid;
            bool active = (i < n);
            unsigned int vk = active ? vals[i] : 0u;
            bool take = active && ((phase == 0) ? (vk < pivot) : (vk == pivot));
            unsigned int m = __ballot_sync(0xFFFFFFFFu, take);
            if (take) {
                int ldr = __ffs(m) - 1;
                int base;
                if (lane == ldr) base = atomicAdd(&s_cnt, __popc(m));
                base = __shfl_sync(m, base, ldr);
                int slot = base + __popc(m & ((1u << lane) - 1u));
                if (slot < 512)
                    s_keys[slot] = ((unsigned long long)vk << 32) | idxs[i];
            }
        }
        __syncthreads();
    }
    int cnt = s_cnt; if (cnt > 512) cnt = 512;
    for (int i = tid; i < 512; i += 1024)
        if (i >= cnt) s_keys[i] = ~0ULL;
    __syncthreads();

    // bitonic sort 512 ascending
    for (unsigned kk2 = 2; kk2 <= 512; kk2 <<= 1) {
        for (unsigned j = kk2 >> 1; j > 0; j >>= 1) {
            for (unsigned i = tid; i < 512; i += 1024) {
                unsigned ixj = i ^ j;
                if (ixj > i) {
                    bool asc = ((i & kk2) == 0);
                    unsigned long long a = s_keys[i], c = s_keys[ixj];
                    if ((a > c) == asc) { s_keys[i] = c; s_keys[ixj] = a; }
                }
            }
            __syncthreads();
        }
    }

    for (int k = tid; k < KK; k += 1024) {
        unsigned long long key = s_keys[k];
        unsigned int vb = 0xFFFFFFFFu - (unsigned int)(key >> 32);
        int idx = (int)(unsigned int)(key & 0xFFFFFFFFu);
        int y = idx / WW;
        int x = idx - y*WW;
        out[OFF_KPTS + ((size_t)b*KK + k)*2 + 0] = (float)x + 0.5f;
        out[OFF_KPTS + ((size_t)b*KK + k)*2 + 1] = (float)y + 0.5f;
        out[OFF_SCORES + (size_t)b*KK + k] = __uint_as_float(vb);
        g_topidx[b*KK + k] = idx;
    }

    if (tid == 0) g_count[b] = 0;   // reset for next graph replay
}

// bilinear descriptor sample + L2 norm. grid (KK/8, BB), block 256 (thread = channel).
// Depth-2 software pipeline on the corner gathers (prefetch kk+1 while computing kk).
__global__ __launch_bounds__(256) void k_sample(const float* __restrict__ desc,
                                                float* __restrict__ out) {
    __shared__ int   s_a0[8];
    __shared__ int   s_a1[8];
    __shared__ int   s_sh[8];
    __shared__ float s_wq[8][4];
    __shared__ float s_norm[8];
    __shared__ float s_inv[8];

    int b  = blockIdx.y;
    int k0 = blockIdx.x * 8;
    int c  = threadIdx.x;
    int lane = c & 31;

    if (c < 8) {
        int idx = g_topidx[b*KK + k0 + c];
        int iy = idx / WW;
        int ix = idx - iy*WW;
        float kx = (float)ix + 0.5f;
        float ky = (float)iy + 0.5f;
        float ux = (kx - 3.5f) / 635.5f;
        float uy = (ky - 3.5f) / 475.5f;
        float gx = ((ux * 2.f - 1.f) + 1.f) * 0.5f * (float)(WCC - 1);
        float gy = ((uy * 2.f - 1.f) + 1.f) * 0.5f * (float)(HCC - 1);
        float x0f = floorf(gx), y0f = floorf(gy);
        float wx = gx - x0f, wy = gy - y0f;
        int x0 = (int)x0f;
        int y0 = (int)y0f;
        int off0 = y0*WCC + x0;
        int off1 = (y0+1)*WCC + x0;
        s_sh[c] = x0 & 3;
        s_a0[c] = off0 >> 2;
        s_a1[c] = off1 >> 2;
        s_wq[c][0] = (1.f - wx) * (1.f - wy);
        s_wq[c][1] = wx * (1.f - wy);
        s_wq[c][2] = (1.f - wx) * wy;
        s_wq[c][3] = wx * wy;
        s_norm[c] = 0.f;
    }
    __syncthreads();

    const float*  dp = desc + ((size_t)b*CC + c) * (HCC*WCC);
    const float4* d4 = reinterpret_cast<const float4*>(dp);

    // prime the pipeline
    float4 q0n = __ldg(d4 + s_a0[0]);
    float4 q1n = __ldg(d4 + s_a1[0]);

    float vv[8];
    #pragma unroll
    for (int kk = 0; kk < 8; ++kk) {
        float4 q0 = q0n, q1 = q1n;
        if (kk < 7) {
            q0n = __ldg(d4 + s_a0[kk+1]);
            q1n = __ldg(d4 + s_a1[kk+1]);
        }
        int sh = s_sh[kk];
        float e00, e01, e10, e11;
        if (sh == 0)      { e00 = q0.x; e01 = q0.y; e10 = q1.x; e11 = q1.y; }
        else if (sh == 1) { e00 = q0.y; e01 = q0.z; e10 = q1.y; e11 = q1.z; }
        else if (sh == 2) { e00 = q0.z; e01 = q0.w; e10 = q1.z; e11 = q1.w; }
        else {
            e00 = q0.w; e10 = q1.w;
            e01 = __ldg(dp + s_a0[kk]*4 + 4);
            e11 = __ldg(dp + s_a1[kk]*4 + 4);
        }
        float v = e00*s_wq[kk][0] + e01*s_wq[kk][1]
                + e10*s_wq[kk][2] + e11*s_wq[kk][3];
        vv[kk] = v;
        float s = v * v;
        #pragma unroll
        for (int o = 16; o > 0; o >>= 1) s += __shfl_xor_sync(0xFFFFFFFFu, s, o);
        if (lane == 0) atomicAdd(&s_norm[kk], s);
    }
    __syncthreads();
    if (c < 8) s_inv[c] = 1.0f / sqrtf(s_norm[c] + 1e-12f);
    __syncthreads();

    float4 o0, o1;
    o0.x = vv[0]*s_inv[0]; o0.y = vv[1]*s_inv[1];
    o0.z = vv[2]*s_inv[2]; o0.w = vv[3]*s_inv[3];
    o1.x = vv[4]*s_inv[4]; o1.y = vv[5]*s_inv[5];
    o1.z = vv[6]*s_inv[6]; o1.w = vv[7]*s_inv[7];
    float4* op = reinterpret_cast<float4*>(out + OFF_SAMPLED + ((size_t)b*CC + c)*KK + k0);
    op[0] = o0;
    op[1] = o1;
}

extern "C" void kernel_launch(void* const* d_in, const int* in_sizes, int n_in,
                              void* d_out, int out_size) {
    const float* heat = (const float*)d_in[0];
    const float* desc = (const float*)d_in[1];
    float* out = (float*)d_out;

    dim3 ngrid(NBY, BB);
    k_nms<<<ngrid, NT>>>(heat, out);

    k_select<<<BB, 1024>>>(out);

    dim3 sgrid(KK / 8, BB);
    k_sample<<<sgrid, 256>>>(desc, out);
}

// round 11
// speedup vs baseline: 1.1590x; 1.0354x over previous
#include <cuda_runtime.h>
#include <cuda_bf16.h>
#include <math.h>

#define BB 16
#define HH 480
#define WW 640
#define HW (HH*WW)
#define CC 256
#define HCC 60
#define WCC 80
#define KK 400
#define CAND_CAP 24576

#define CH 10               // output rows per block (best measured config)
#define NBY (HH / CH)       // 48
#define NT 160              // threads per block = 640/4 columns
#define SBUF 1024           // per-block candidate staging capacity

// output layout: kpts (16,400,2) | scores (16,400) | sampled (16,256,400) | heatmap (16,1,480,640)
#define OFF_KPTS 0
#define OFF_SCORES (BB*KK*2)
#define OFF_SAMPLED (OFF_SCORES + BB*KK)
#define OFF_HEAT (OFF_SAMPLED + BB*CC*KK)

__device__ unsigned int g_cval[BB*CAND_CAP];
__device__ unsigned int g_cidx[BB*CAND_CAP];
__device__ int g_count[BB];      // zero at load; re-zeroed by k_select tail each replay
__device__ int g_topidx[BB*KK];

// Fused NMS: heatmap copy + separable 7x7 max + compaction.
// grid (NBY, BB), block 160. Thread = 4 consecutive columns (one float4).
__global__ __launch_bounds__(NT) void k_nms(const float* __restrict__ h,
                                            float* __restrict__ out) {
    __shared__ unsigned int s_val[SBUF];
    __shared__ unsigned int s_idx[SBUF];
    __shared__ int s_cnt;
    __shared__ int s_base;

    int b   = blockIdx.y;
    int ty0 = blockIdx.x * CH;
    int tid = threadIdx.x;
    if (tid == 0) s_cnt = 0;
    __syncthreads();

    const float4* hb4 = reinterpret_cast<const float4*>(h + (size_t)b*HW);
    float4*       ob4 = reinterpret_cast<float4*>(out + OFF_HEAT + (size_t)b*HW);
    int xb = tid * 4;

    float4 zero4 = make_float4(0.f, 0.f, 0.f, 0.f);
    float4 w0=zero4,w1=zero4,w2=zero4,w3=zero4,w4=zero4,w5=zero4,w6=zero4;
    float4 d0=zero4,d1=zero4,d2=zero4;

    #pragma unroll
    for (int t = 0; t < CH + 6; ++t) {
        int yy = ty0 - 3 + t;
        float4 qm = zero4, qc = zero4, qp = zero4;
        if (yy >= 0 && yy < HH) {
            int rb = yy * (WW/4);
            qc = __ldg(hb4 + rb + tid);
            if (tid > 0)      qm = __ldg(hb4 + rb + tid - 1);
            if (tid < NT - 1) qp = __ldg(hb4 + rb + tid + 1);
            if (t >= 3 && t < CH + 3) ob4[rb + tid] = qc;
        }
        float p1 = fmaxf(qm.y, qm.z);
        float p2 = fmaxf(qm.z, qm.w);
        float p3 = fmaxf(qm.w, qc.x);
        float p4 = fmaxf(qc.x, qc.y);
        float p5 = fmaxf(qc.y, qc.z);
        float p6 = fmaxf(qc.z, qc.w);
        float p7 = fmaxf(qc.w, qp.x);
        float p8 = fmaxf(qp.x, qp.y);
        float4 rm;
        rm.x = fmaxf(fmaxf(p1, p3), fmaxf(p5, qc.w));
        rm.y = fmaxf(fmaxf(p2, p4), fmaxf(p6, qp.x));
        rm.z = fmaxf(fmaxf(p3, p5), fmaxf(p7, qp.y));
        rm.w = fmaxf(fmaxf(p4, p6), fmaxf(p8, qp.z));

        float4 vcand = d0;
        d0 = d1; d1 = d2; d2 = qc;
        w0 = w1; w1 = w2; w2 = w3; w3 = w4; w4 = w5; w5 = w6; w6 = rm;

        if (t >= 6) {
            int yc = yy - 3;
            if (yc >= 4 && yc < HH - 4) {
                float4 m;
                m.x = fmaxf(fmaxf(fmaxf(w0.x,w1.x),fmaxf(w2.x,w3.x)),
                            fmaxf(fmaxf(w4.x,w5.x),w6.x));
                m.y = fmaxf(fmaxf(fmaxf(w0.y,w1.y),fmaxf(w2.y,w3.y)),
                            fmaxf(fmaxf(w4.y,w5.y),w6.y));
                m.z = fmaxf(fmaxf(fmaxf(w0.z,w1.z),fmaxf(w2.z,w3.z)),
                            fmaxf(fmaxf(w4.z,w5.z),w6.z));
                m.w = fmaxf(fmaxf(fmaxf(w0.w,w1.w),fmaxf(w2.w,w3.w)),
                            fmaxf(fmaxf(w4.w,w5.w),w6.w));
                float vj[4] = {vcand.x, vcand.y, vcand.z, vcand.w};
                float mj[4] = {m.x, m.y, m.z, m.w};
                #pragma unroll
                for (int j = 0; j < 4; ++j) {
                    int x = xb + j;
                    if (x >= 4 && x < WW-4 && vj[j] > 0.f && vj[j] >= mj[j]) {
                        int p = atomicAdd(&s_cnt, 1);
                        if (p < SBUF) {
                            s_val[p] = 0xFFFFFFFFu - __float_as_uint(vj[j]);
                            s_idx[p] = (unsigned)(yc*WW + x);
                        }
                    }
                }
            }
        }
    }

    __syncthreads();
    int cnt = s_cnt; if (cnt > SBUF) cnt = SBUF;
    if (tid == 0) s_base = atomicAdd(&g_count[b], cnt);
    __syncthreads();
    int base = s_base;
    for (int i = tid; i < cnt; i += NT) {
        int slot = base + i;
        if (slot < CAND_CAP) {
            g_cval[b*CAND_CAP + slot] = s_val[i];
            g_cidx[b*CAND_CAP + slot] = s_idx[i];
        }
    }
}

// exact per-batch top-K: TWO-pass wide radix-select (22-bit pivot prefix);
// the selected 22-bit bin holds only a handful of keys, so gather
// (vk>>10) < prefix  (strictly-less: provably < KK)  plus  == prefix, and
// bitonic-sort the <=512 gathered (value,idx) keys for the exact order.
__global__ __launch_bounds__(1024) void k_select(float* __restrict__ out) {
    __shared__ unsigned int bins[2048];
    __shared__ int s_warp[32];
    __shared__ unsigned int s_bin;
    __shared__ int s_newrank;
    __shared__ unsigned long long s_keys[512];
    __shared__ int s_cnt;

    int b = blockIdx.x;
    int tid = threadIdx.x;
    int lane = tid & 31, wid = tid >> 5;
    int n = g_count[b]; if (n > CAND_CAP) n = CAND_CAP;
    const unsigned int* vals = g_cval + (size_t)b*CAND_CAP;
    const unsigned int* idxs = g_cidx + (size_t)b*CAND_CAP;

    int nIter = (n + 1023) >> 10;
    unsigned int pivot22 = 0x3FFFFFu;    // if n < KK: gather everything
    int rank = KK;

    if (n >= KK) {
        unsigned int prefix = 0;
        #pragma unroll
        for (int p = 0; p < 2; ++p) {
            int shift = (p == 0) ? 21 : 10;

            for (int i = tid; i < 2048; i += 1024) bins[i] = 0;
            __syncthreads();

            for (int it = 0; it < nIter; ++it) {      // uniform trip count
                int i = (it << 10) + tid;
                bool active = (i < n);
                unsigned int vk = active ? vals[i] : 0u;
                bool ok = active && ((p == 0) || ((vk >> 21) == prefix));
                unsigned int bin = (vk >> shift) & 2047u;
                unsigned int m = __ballot_sync(0xFFFFFFFFu, ok);
                if (ok) {
                    unsigned int peers = __match_any_sync(m, bin);
                    int ldr = __ffs(peers) - 1;
                    if (lane == ldr) atomicAdd(&bins[bin], (unsigned)__popc(peers));
                }
            }
            __syncthreads();

            // parallel scan over 2048 bins: thread owns bins[2t], bins[2t+1]
            int c0 = (int)bins[2*tid];
            int c1 = (int)bins[2*tid + 1];
            int s = c0 + c1;
            int v2 = s;
            #pragma unroll
            for (int o = 1; o < 32; o <<= 1) {
                int t = __shfl_up_sync(0xFFFFFFFFu, v2, o);
                if (lane >= o) v2 += t;
            }
            if (lane == 31) s_warp[wid] = v2;
            __syncthreads();
            if (wid == 0) {
                int ws = s_warp[lane];
                #pragma unroll
                for (int o = 1; o < 32; o <<= 1) {
                    int t = __shfl_up_sync(0xFFFFFFFFu, ws, o);
                    if (lane >= o) ws += t;
                }
                s_warp[lane] = ws;
            }
            __syncthreads();
            int incl = v2 + (wid > 0 ? s_warp[wid - 1] : 0);
            int excl = incl - s;
            if (rank > excl && rank <= excl + c0) {
                s_bin = (unsigned)(2*tid); s_newrank = rank - excl;
            } else if (rank > excl + c0 && rank <= incl) {
                s_bin = (unsigned)(2*tid + 1); s_newrank = rank - excl - c0;
            }
            __syncthreads();
            prefix = (p == 0) ? s_bin : ((prefix << 11) | s_bin);
            rank = s_newrank;
            __syncthreads();
        }
        pivot22 = prefix;
    }

    // gather: strictly-less on 22-bit prefix (count < KK guaranteed), then equals
    if (tid == 0) s_cnt = 0;
    __syncthreads();
    #pragma unroll
    for (int phase = 0; phase < 2; ++phase) {
        for (int it = 0; it < nIter; ++it) {          // uniform trip count
            int i = (it << 10) + tid;
            bool active = (i < n);
            unsigned int vk = active ? vals[i] : 0u;
            unsigned int hi = vk >> 10;
            bool take = active && ((phase == 0) ? (hi < pivot22) : (hi == pivot22));
            unsigned int m = __ballot_sync(0xFFFFFFFFu, take);
            if (take) {
                int ldr = __ffs(m) - 1;
                int base;
                if (lane == ldr) base = atomicAdd(&s_cnt, __popc(m));
                base = __shfl_sync(m, base, ldr);
                int slot = base + __popc(m & ((1u << lane) - 1u));
                if (slot < 512)
                    s_keys[slot] = ((unsigned long long)vk << 32) | idxs[i];
            }
        }
        __syncthreads();
    }
    int cnt = s_cnt; if (cnt > 512) cnt = 512;
    for (int i = tid; i < 512; i += 1024)
        if (i >= cnt) s_keys[i] = ~0ULL;
    __syncthreads();

    // bitonic sort 512 ascending on (value,idx)
    for (unsigned kk2 = 2; kk2 <= 512; kk2 <<= 1) {
        for (unsigned j = kk2 >> 1; j > 0; j >>= 1) {
            for (unsigned i = tid; i < 512; i += 1024) {
                unsigned ixj = i ^ j;
                if (ixj > i) {
                    bool asc = ((i & kk2) == 0);
                    unsigned long long a = s_keys[i], c = s_keys[ixj];
                    if ((a > c) == asc) { s_keys[i] = c; s_keys[ixj] = a; }
                }
            }
            __syncthreads();
        }
    }

    for (int k = tid; k < KK; k += 1024) {
        unsigned long long key = s_keys[k];
        unsigned int vb = 0xFFFFFFFFu - (unsigned int)(key >> 32);
        int idx = (int)(unsigned int)(key & 0xFFFFFFFFu);
        int y = idx / WW;
        int x = idx - y*WW;
        out[OFF_KPTS + ((size_t)b*KK + k)*2 + 0] = (float)x + 0.5f;
        out[OFF_KPTS + ((size_t)b*KK + k)*2 + 1] = (float)y + 0.5f;
        out[OFF_SCORES + (size_t)b*KK + k] = __uint_as_float(vb);
        g_topidx[b*KK + k] = idx;
    }

    if (tid == 0) g_count[b] = 0;   // reset for next graph replay
}

// bilinear descriptor sample + L2 norm. grid (KK/8, BB), block 256 (thread = channel).
// float4 corner gather + contiguous float4 output writes. (R7-proven form.)
__global__ __launch_bounds__(256) void k_sample(const float* __restrict__ desc,
                                                float* __restrict__ out) {
    __shared__ int   s_a0[8];
    __shared__ int   s_a1[8];
    __shared__ int   s_sh[8];
    __shared__ float s_wq[8][4];
    __shared__ float s_norm[8];
    __shared__ float s_inv[8];

    int b  = blockIdx.y;
    int k0 = blockIdx.x * 8;
    int c  = threadIdx.x;
    int lane = c & 31;

    if (c < 8) {
        int idx = g_topidx[b*KK + k0 + c];
        int iy = idx / WW;
        int ix = idx - iy*WW;
        float kx = (float)ix + 0.5f;
        float ky = (float)iy + 0.5f;
        float ux = (kx - 3.5f) / 635.5f;
        float uy = (ky - 3.5f) / 475.5f;
        float gx = ((ux * 2.f - 1.f) + 1.f) * 0.5f * (float)(WCC - 1);
        float gy = ((uy * 2.f - 1.f) + 1.f) * 0.5f * (float)(HCC - 1);
        float x0f = floorf(gx), y0f = floorf(gy);
        float wx = gx - x0f, wy = gy - y0f;
        int x0 = (int)x0f;
        int y0 = (int)y0f;
        int off0 = y0*WCC + x0;
        int off1 = (y0+1)*WCC + x0;
        s_sh[c] = x0 & 3;
        s_a0[c] = off0 >> 2;
        s_a1[c] = off1 >> 2;
        s_wq[c][0] = (1.f - wx) * (1.f - wy);
        s_wq[c][1] = wx * (1.f - wy);
        s_wq[c][2] = (1.f - wx) * wy;
        s_wq[c][3] = wx * wy;
        s_norm[c] = 0.f;
    }
    __syncthreads();

    const float*  dp = desc + ((size_t)b*CC + c) * (HCC*WCC);
    const float4* d4 = reinterpret_cast<const float4*>(dp);

    float vv[8];
    #pragma unroll
    for (int kk = 0; kk < 8; ++kk) {
        int a0 = s_a0[kk], a1 = s_a1[kk], sh = s_sh[kk];
        float4 q0 = __ldg(d4 + a0);
        float4 q1 = __ldg(d4 + a1);
        float e00, e01, e10, e11;
        if (sh == 0)      { e00 = q0.x; e01 = q0.y; e10 = q1.x; e11 = q1.y; }
        else if (sh == 1) { e00 = q0.y; e01 = q0.z; e10 = q1.y; e11 = q1.z; }
        else if (sh == 2) { e00 = q0.z; e01 = q0.w; e10 = q1.z; e11 = q1.w; }
        else {
            e00 = q0.w; e10 = q1.w;
            e01 = __ldg(dp + a0*4 + 4);
            e11 = __ldg(dp + a1*4 + 4);
        }
        float v = e00*s_wq[kk][0] + e01*s_wq[kk][1]
                + e10*s_wq[kk][2] + e11*s_wq[kk][3];
        vv[kk] = v;
        float s = v * v;
        #pragma unroll
        for (int o = 16; o > 0; o >>= 1) s += __shfl_xor_sync(0xFFFFFFFFu, s, o);
        if (lane == 0) atomicAdd(&s_norm[kk], s);
    }
    __syncthreads();
    if (c < 8) s_inv[c] = 1.0f / sqrtf(s_norm[c] + 1e-12f);
    __syncthreads();

    float4 o0, o1;
    o0.x = vv[0]*s_inv[0]; o0.y = vv[1]*s_inv[1];
    o0.z = vv[2]*s_inv[2]; o0.w = vv[3]*s_inv[3];
    o1.x = vv[4]*s_inv[4]; o1.y = vv[5]*s_inv[5];
    o1.z = vv[6]*s_inv[6]; o1.w = vv[7]*s_inv[7];
    float4* op = reinterpret_cast<float4*>(out + OFF_SAMPLED + ((size_t)b*CC + c)*KK + k0);
    op[0] = o0;
    op[1] = o1;
}

extern "C" void kernel_launch(void* const* d_in, const int* in_sizes, int n_in,
                              void* d_out, int out_size) {
    const float* heat = (const float*)d_in[0];
    const float* desc = (const float*)d_in[1];
    float* out = (float*)d_out;

    dim3 ngrid(NBY, BB);
    k_nms<<<ngrid, NT>>>(heat, out);

    k_select<<<BB, 1024>>>(out);

    dim3 sgrid(KK / 8, BB);
    k_sample<<<sgrid, 256>>>(desc, out);
}